// round 13
// baseline (speedup 1.0000x reference)
#include <cuda_runtime.h>
#include <cuda_bf16.h>

// ann2_snn1: sigmoid -> feature-uniform dual-exp IIR -> W proj (500->10) -> LIF spikes
// inputs [64,500,1024] f32; a1,a2 [500]; W [10,500]; b [10]; out [64,10,1024] f32
//
// IIR coeffs are feature-uniform => IIR commutes with the projection:
//   W @ IIR(sig(x)) == IIR(W @ sig(x))
//
// R12 post-mortem: proj is exposed-DRAM-latency bound; unroll 20 (MLP) took it
// 50->41us but warps/SM is grid-limited at 13.8 (512 blocks). R13: split the
// f-reduction in half across 2 blocks (grid 1024, ~27.7 warps/SM, 2x latency
// hiding); iir stage-in sums the two partial buffers off the serial chain.
// Kernel 2 serial chain: arithmetically identical to R10-R12 (25.4us).

#define B_ 64
#define F_ 500
#define T_ 1024
#define O_ 10
#define CH (B_ * O_)     // 640 channels
#define FHALF (F_ / 2)   // 250

// partial scratch: u_half[t][b*10+o]  (2.62 MB each, L2-resident)
__device__ float g_u[(size_t)T_ * CH];
__device__ float g_u2[(size_t)T_ * CH];

// ---------------------------------------------------------------------------
// Kernel 1: partial projection over one f-half.
//   u_half[t, b, o] = sum_{f in half} W[o,f] * sigmoid(inputs[b, f, t])
// grid = (T/128, B, 2), block = 128 (one t per thread)
// ---------------------------------------------------------------------------
__global__ void __launch_bounds__(128) proj_kernel(const float* __restrict__ in,
                                                   const float* __restrict__ W) {
    __shared__ float Wsh[FHALF * 12];   // 250 rows padded to 12 -> 3x float4, 12KB

    const int tid  = threadIdx.x;
    const int b    = blockIdx.y;
    const int half = blockIdx.z;
    const int f0   = half * FHALF;
    const int t    = blockIdx.x * 128 + tid;

    for (int i = tid; i < FHALF * 12; i += 128) {
        int f = i / 12;
        int o = i - f * 12;
        Wsh[i] = (o < O_) ? W[o * F_ + f0 + f] : 0.0f;
    }
    __syncthreads();

    const float* row = in + (size_t)b * (F_ * T_) + (size_t)f0 * T_ + t;
    const float4* W4 = (const float4*)Wsh;

    float acc0 = 0.f, acc1 = 0.f, acc2 = 0.f, acc3 = 0.f, acc4 = 0.f;
    float acc5 = 0.f, acc6 = 0.f, acc7 = 0.f, acc8 = 0.f, acc9 = 0.f;

    // unroll 25 (250 = 25*10): 25 independent LDGs in flight per warp
#pragma unroll 25
    for (int f = 0; f < FHALF; f++) {
        float x = __ldg(row + (size_t)f * T_);
        float e = __expf(-x);
        float s = __fdividef(1.0f, 1.0f + e);

        float4 w0 = W4[f * 3 + 0];
        float4 w1 = W4[f * 3 + 1];
        float4 w2 = W4[f * 3 + 2];

        acc0 += w0.x * s;  acc1 += w0.y * s;  acc2 += w0.z * s;  acc3 += w0.w * s;
        acc4 += w1.x * s;  acc5 += w1.y * s;  acc6 += w1.z * s;  acc7 += w1.w * s;
        acc8 += w2.x * s;  acc9 += w2.y * s;
    }

    float* base = half ? g_u2 : g_u;
    float* up = base + (size_t)t * CH + b * O_;
    up[0] = acc0;  up[1] = acc1;  up[2] = acc2;  up[3] = acc3;  up[4] = acc4;
    up[5] = acc5;  up[6] = acc6;  up[7] = acc7;  up[8] = acc8;  up[9] = acc9;
}

// ---------------------------------------------------------------------------
// Kernel 2: smem-staged serial IIR + LIF.
// Stage-in now sums the two f-half partial buffers (off the serial chain);
// the 1024-step serial chain is arithmetically identical to R10-R12.
// grid = 20 blocks x 128 threads; block owns 32 channels; warp 0 runs chain.
// ---------------------------------------------------------------------------
#define TILE_ 16
#define SMEM_BYTES (T_ * 32 * sizeof(float))   // 131072

__global__ void __launch_bounds__(128) iir_lif_kernel(const float* __restrict__ a1p,
                                                      const float* __restrict__ a2p,
                                                      const float* __restrict__ bias,
                                                      float* __restrict__ out) {
    extern __shared__ float sm[];   // sm[t*32 + lane]

    const int tid = threadIdx.x;
    const int ch0 = blockIdx.x * 32;

    // Phase 1: coalesced stage-in + halves sum. 8 float4 per t-row.
    {
        float4* dst = (float4*)sm;
        for (int i = tid; i < T_ * 8; i += 128) {
            int t = i >> 3;
            int j = i & 7;
            size_t off = (size_t)t * CH + ch0 + j * 4;
            float4 a = *(const float4*)(g_u  + off);
            float4 c = *(const float4*)(g_u2 + off);
            dst[i] = make_float4(a.x + c.x, a.y + c.y, a.z + c.z, a.w + c.w);
        }
    }
    __syncthreads();
    if (tid >= 32) return;          // warps 1-3 done (no further barriers)

    const int ch = ch0 + tid;
    const int b  = ch / O_;
    const int o  = ch - b * O_;

    const float a1 = __ldg(a1p);    // feature-uniform
    const float a2 = __ldg(a2p);
    const float bo = __ldg(bias + o);
    const float dm = 0.7788007830714049f;   // exp(-1/4)

    float y1 = 0.f, y2 = 0.f, v = 0.f;
    bool fired = false;

    float* orow = out + (size_t)b * (O_ * T_) + (size_t)o * T_;
    const float* mysm = sm + tid;   // stride 32 floats per t, conflict-free

    for (int t0 = 0; t0 < T_; t0 += TILE_) {
        // pull 16 steps from smem (29-cyc LDS, batched; independent of chain)
        float xt[TILE_];
#pragma unroll
        for (int i = 0; i < TILE_; i++) xt[i] = mysm[(t0 + i) * 32];

        float sbuf[TILE_];
#pragma unroll
        for (int i = 0; i < TILE_; i++) {
            // IIR: exact rounding order of the reference (mul, mul, add, add)
            float y = __fadd_rn(__fadd_rn(__fmul_rn(a1, y1), __fmul_rn(a2, y2)), xt[i]);
            y2 = y1;
            y1 = y;
            float psc = __fadd_rn(y, bo);
            // leak path computed in parallel with the fired-predicate
            float vleak = __fadd_rn(__fmul_rn(dm, v), psc);
            v = fired ? psc : vleak;
            fired = (v > 1.0f);
            sbuf[i] = fired ? 1.0f : 0.0f;
        }

        // vectorized stores, off the critical path
        float4* o4 = (float4*)(orow + t0);
#pragma unroll
        for (int i = 0; i < TILE_ / 4; i++)
            o4[i] = make_float4(sbuf[4*i], sbuf[4*i+1], sbuf[4*i+2], sbuf[4*i+3]);
    }
}

// ---------------------------------------------------------------------------
extern "C" void kernel_launch(void* const* d_in, const int* in_sizes, int n_in,
                              void* d_out, int out_size) {
    (void)in_sizes; (void)n_in; (void)out_size;
    const float* inputs = (const float*)d_in[0];   // [64, 500, 1024]
    const float* a1     = (const float*)d_in[1];   // [500]
    const float* a2     = (const float*)d_in[2];   // [500]
    const float* W      = (const float*)d_in[3];   // [10, 500]
    const float* bias   = (const float*)d_in[4];   // [10]
    float*       out    = (float*)d_out;           // [64, 10, 1024]

    // 128 KB dynamic smem for the stage-in buffer (host-side config; no alloc)
    cudaFuncSetAttribute(iir_lif_kernel,
                         cudaFuncAttributeMaxDynamicSharedMemorySize, SMEM_BYTES);

    dim3 g1(T_ / 128, B_, 2);
    proj_kernel<<<g1, 128>>>(inputs, W);

    iir_lif_kernel<<<CH / 32, 128, SMEM_BYTES>>>(a1, a2, bias, out);
}

// round 16
// speedup vs baseline: 1.1128x; 1.1128x over previous
#include <cuda_runtime.h>
#include <cuda_bf16.h>

// ann2_snn1: sigmoid -> feature-uniform dual-exp IIR -> W proj (500->10) -> LIF spikes
// inputs [64,500,1024] f32; a1,a2 [500]; W [10,500]; b [10]; out [64,10,1024] f32
//
// IIR coeffs are feature-uniform => IIR commutes with the projection:
//   W @ IIR(sig(x)) == IIR(W @ sig(x))
//
// R13 post-mortem: splitting f across BLOCKS doubled warps/SM and cut proj to
// ~34us (occupancy theory confirmed) but the two-buffer merge in the iir
// stage-in cost +28us. R14: split f WITHIN a 256-thread block instead -
// same 27.7 warps/SM, merge is a one-time 5KB smem exchange, single g_u.
// Kernel 2: byte-identical to R12 (measured 25.4us).
// Numerics: the lo+hi halves-sum reassociation measured rel_err 0.0 in R13.

#define B_ 64
#define F_ 500
#define T_ 1024
#define O_ 10
#define CH (B_ * O_)     // 640 channels
#define FHALF (F_ / 2)   // 250

// scratch: u[t][b*10+o]  (2.62 MB, L2-resident)
__device__ float g_u[(size_t)T_ * CH];

// ---------------------------------------------------------------------------
// Kernel 1: u[t, b, o] = sum_f W[o,f] * sigmoid(inputs[b, f, t])
// block = 256: threads 0-127 reduce f in [0,250) for t-tile, threads 128-255
// reduce f in [250,500) for the SAME t-tile; smem exchange sums the halves.
// grid = (T/128, B) = 512 blocks x 8 warps -> 27.7 warps/SM.
// ---------------------------------------------------------------------------
__global__ void __launch_bounds__(256) proj_kernel(const float* __restrict__ in,
                                                   const float* __restrict__ W) {
    __shared__ float Wsh[F_ * 12];          // 24KB: padded rows -> 3x float4
    __shared__ float partial[128 * O_];     // 5KB: upper half's partials

    const int tid   = threadIdx.x;
    const int lane  = tid & 127;            // t within tile
    const int group = tid >> 7;             // 0: f[0,250)  1: f[250,500)
    const int b     = blockIdx.y;
    const int t     = blockIdx.x * 128 + lane;
    const int f0    = group * FHALF;

    for (int i = tid; i < F_ * 12; i += 256) {
        int f = i / 12;
        int o = i - f * 12;
        Wsh[i] = (o < O_) ? W[o * F_ + f] : 0.0f;
    }
    __syncthreads();

    const float* row = in + (size_t)b * (F_ * T_) + (size_t)f0 * T_ + t;
    const float4* W4 = (const float4*)(Wsh + f0 * 12);

    float acc0 = 0.f, acc1 = 0.f, acc2 = 0.f, acc3 = 0.f, acc4 = 0.f;
    float acc5 = 0.f, acc6 = 0.f, acc7 = 0.f, acc8 = 0.f, acc9 = 0.f;

    // unroll 25 (250 = 25*10): 25 independent LDGs in flight per warp
#pragma unroll 25
    for (int f = 0; f < FHALF; f++) {
        float x = __ldg(row + (size_t)f * T_);
        float e = __expf(-x);
        float s = __fdividef(1.0f, 1.0f + e);

        float4 w0 = W4[f * 3 + 0];
        float4 w1 = W4[f * 3 + 1];
        float4 w2 = W4[f * 3 + 2];

        acc0 += w0.x * s;  acc1 += w0.y * s;  acc2 += w0.z * s;  acc3 += w0.w * s;
        acc4 += w1.x * s;  acc5 += w1.y * s;  acc6 += w1.z * s;  acc7 += w1.w * s;
        acc8 += w2.x * s;  acc9 += w2.y * s;
    }

    // upper half publishes partials; lower half sums (lo + hi, R13-verified)
    if (group == 1) {
        float* p = partial + lane * O_;
        p[0] = acc0;  p[1] = acc1;  p[2] = acc2;  p[3] = acc3;  p[4] = acc4;
        p[5] = acc5;  p[6] = acc6;  p[7] = acc7;  p[8] = acc8;  p[9] = acc9;
    }
    __syncthreads();
    if (group == 0) {
        const float* p = partial + lane * O_;
        float* up = g_u + (size_t)t * CH + b * O_;
        up[0] = acc0 + p[0];  up[1] = acc1 + p[1];  up[2] = acc2 + p[2];
        up[3] = acc3 + p[3];  up[4] = acc4 + p[4];  up[5] = acc5 + p[5];
        up[6] = acc6 + p[6];  up[7] = acc7 + p[7];  up[8] = acc8 + p[8];
        up[9] = acc9 + p[9];
    }
}

// ---------------------------------------------------------------------------
// Kernel 2: smem-staged serial IIR + LIF.   [byte-identical to R12, 25.4us]
// grid = 20 blocks x 128 threads. Block owns 32 channels.
// Phase 1: all 4 warps stage u[0..1023][ch0..ch0+31] (128 KB) into smem.
// Phase 2: warp 0 runs the 1024-step serial chain from 29-cyc LDS.
// ---------------------------------------------------------------------------
#define TILE_ 16
#define SMEM_BYTES (T_ * 32 * sizeof(float))   // 131072

__global__ void __launch_bounds__(128) iir_lif_kernel(const float* __restrict__ a1p,
                                                      const float* __restrict__ a2p,
                                                      const float* __restrict__ bias,
                                                      float* __restrict__ out) {
    extern __shared__ float sm[];   // sm[t*32 + lane]

    const int tid = threadIdx.x;
    const int ch0 = blockIdx.x * 32;

    // Phase 1: coalesced stage-in. 8 float4 per t-row; i covers T_*8 = 8192 vecs.
    {
        float4* dst = (float4*)sm;
        for (int i = tid; i < T_ * 8; i += 128) {
            int t = i >> 3;
            int j = i & 7;
            dst[i] = *(const float4*)(g_u + (size_t)t * CH + ch0 + j * 4);
        }
    }
    __syncthreads();
    if (tid >= 32) return;          // warps 1-3 done (no further barriers)

    const int ch = ch0 + tid;
    const int b  = ch / O_;
    const int o  = ch - b * O_;

    const float a1 = __ldg(a1p);    // feature-uniform
    const float a2 = __ldg(a2p);
    const float bo = __ldg(bias + o);
    const float dm = 0.7788007830714049f;   // exp(-1/4)

    float y1 = 0.f, y2 = 0.f, v = 0.f;
    bool fired = false;

    float* orow = out + (size_t)b * (O_ * T_) + (size_t)o * T_;
    const float* mysm = sm + tid;   // stride 32 floats per t, conflict-free

    for (int t0 = 0; t0 < T_; t0 += TILE_) {
        // pull 16 steps from smem (29-cyc LDS, batched; independent of chain)
        float xt[TILE_];
#pragma unroll
        for (int i = 0; i < TILE_; i++) xt[i] = mysm[(t0 + i) * 32];

        float sbuf[TILE_];
#pragma unroll
        for (int i = 0; i < TILE_; i++) {
            // IIR: exact rounding order of the reference (mul, mul, add, add)
            float y = __fadd_rn(__fadd_rn(__fmul_rn(a1, y1), __fmul_rn(a2, y2)), xt[i]);
            y2 = y1;
            y1 = y;
            float psc = __fadd_rn(y, bo);
            // leak path computed in parallel with the fired-predicate
            float vleak = __fadd_rn(__fmul_rn(dm, v), psc);
            v = fired ? psc : vleak;
            fired = (v > 1.0f);
            sbuf[i] = fired ? 1.0f : 0.0f;
        }

        // vectorized stores, off the critical path
        float4* o4 = (float4*)(orow + t0);
#pragma unroll
        for (int i = 0; i < TILE_ / 4; i++)
            o4[i] = make_float4(sbuf[4*i], sbuf[4*i+1], sbuf[4*i+2], sbuf[4*i+3]);
    }
}

// ---------------------------------------------------------------------------
extern "C" void kernel_launch(void* const* d_in, const int* in_sizes, int n_in,
                              void* d_out, int out_size) {
    (void)in_sizes; (void)n_in; (void)out_size;
    const float* inputs = (const float*)d_in[0];   // [64, 500, 1024]
    const float* a1     = (const float*)d_in[1];   // [500]
    const float* a2     = (const float*)d_in[2];   // [500]
    const float* W      = (const float*)d_in[3];   // [10, 500]
    const float* bias   = (const float*)d_in[4];   // [10]
    float*       out    = (float*)d_out;           // [64, 10, 1024]

    // 128 KB dynamic smem for the stage-in buffer (host-side config; no alloc)
    cudaFuncSetAttribute(iir_lif_kernel,
                         cudaFuncAttributeMaxDynamicSharedMemorySize, SMEM_BYTES);

    dim3 g1(T_ / 128, B_);
    proj_kernel<<<g1, 256>>>(inputs, W);

    iir_lif_kernel<<<CH / 32, 128, SMEM_BYTES>>>(a1, a2, bias, out);
}